// round 3
// baseline (speedup 1.0000x reference)
#include <cuda_runtime.h>
#include <stdint.h>

// Problem constants
#define BATCH   32768
#define NBOOKS  16
#define KCODES  256
#define DDIM    64
#define DECAY_F   0.99f
// reference computes (1.0 - 0.99) in f64 then rounds to f32 when applied
#define OMDECAY_F 0.010000000000000009f
#define EPS_F     1e-5f

// Output packing (tuple concatenated, f32):
//   codes [B,16] | recon [B,1024] | new_codebooks [16,256,64] | new_count [16,256] | new_weight [16,256,64]
#define OFF_CODES 0LL
#define OFF_RECON (32768LL * 16)                       // 524288
#define OFF_CB    (OFF_RECON + 32768LL * 1024)         // 34078720
#define OFF_CNT   (OFF_CB + 16LL * 256 * 64)           // 34340864
#define OFF_W     (OFF_CNT + 16LL * 256)               // 34344960

// Scratch (no cudaMalloc allowed)
__device__ float g_counts[NBOOKS * KCODES];
__device__ float g_dw[NBOOKS * KCODES * DDIM];

// ---------------- shared memory layout (floats) ----------------
// Xdup : float2[64][128]  duplicated x for f32x2 operands : 16384 floats @ 0
// Cs   : float[64][256]   codebook transposed [d][k]      : 16384 floats @ 16384
// cc   : float[256]       ||c_k||^2                       : 256    floats @ 32768
// Xp   : float[128][68]   plain x, padded stride          : 8704   floats @ 33024
// As   : float[128]       ||x_r||^2 (reference-order fp32): 128    floats @ 41728
#define SM_XDUP 0
#define SM_CS   16384
#define SM_CC   32768
#define SM_XP   33024
#define SM_AS   41728
#define SM_FLOATS 41856
#define SM_BYTES  (SM_FLOATS * 4)   // 167424

__device__ __forceinline__ unsigned long long ffma2(unsigned long long a,
                                                    unsigned long long b,
                                                    unsigned long long c) {
    unsigned long long d;
    asm("fma.rn.f32x2 %0, %1, %2, %3;" : "=l"(d) : "l"(a), "l"(b), "l"(c));
    return d;
}
__device__ __forceinline__ float f2lo(unsigned long long a) {
    return __uint_as_float((unsigned)(a & 0xffffffffull));
}
__device__ __forceinline__ float f2hi(unsigned long long a) {
    return __uint_as_float((unsigned)(a >> 32));
}

// Emulate reference fp32 elementwise: r = fl( fl(A - fl(2*dot)) + cc )
__device__ __forceinline__ float rdist(float A, float dot, float ccv) {
    return __fadd_rn(__fsub_rn(A, __fmul_rn(2.0f, dot)), ccv);
}

__global__ void zero_kernel() {
    int i = blockIdx.x * blockDim.x + threadIdx.x;
    if (i < NBOOKS * KCODES) g_counts[i] = 0.0f;
    if (i < NBOOKS * KCODES * DDIM) g_dw[i] = 0.0f;
}

// One CTA: book n = blockIdx.y, rows [blockIdx.x*128, +128). 512 threads.
// Thread tile: 8 rows x 8 cols, cols strided so LDS.128 on Cs is conflict-free.
__global__ void __launch_bounds__(512, 1)
assign_kernel(const float* __restrict__ x, const float* __restrict__ cbk,
              float* codes_out)
{
    extern __shared__ float sm[];
    float* Xd = sm + SM_XDUP;   // float2[64][128] viewed as floats
    float* Cs = sm + SM_CS;
    float* cc = sm + SM_CC;
    float* Xp = sm + SM_XP;
    float* As = sm + SM_AS;

    const int tid  = threadIdx.x;
    const int n    = blockIdx.y;
    const int row0 = blockIdx.x * 128;

    // ---- load x tile (coalesced global -> Xp, conflict-free) ----
    for (int t = tid; t < 2048; t += 512) {
        int r = t >> 4, q = t & 15;
        float4 v = *(const float4*)(x + (size_t)(row0 + r) * 1024 + n * 64 + q * 4);
        *(float4*)(Xp + r * 68 + q * 4) = v;
    }
    // ---- load codebook transposed: lane-distinct k (mod 32) -> conflict-free STS ----
    for (int t = tid; t < 4096; t += 512) {
        int k = (t & 31) | (((t >> 5) & 7) << 5);
        int q = t >> 8;
        float4 v = *(const float4*)(cbk + ((size_t)n * 256 + k) * 64 + q * 4);
        Cs[(q * 4 + 0) * 256 + k] = v.x;
        Cs[(q * 4 + 1) * 256 + k] = v.y;
        Cs[(q * 4 + 2) * 256 + k] = v.z;
        Cs[(q * 4 + 3) * 256 + k] = v.w;
    }
    __syncthreads();
    // ---- build duplicated-x (operand for fma.f32x2) ----
    for (int t = tid; t < 8192; t += 512) {
        int r = (t & 31) | (((t >> 5) & 3) << 5);
        int d = t >> 7;
        float v = Xp[r * 68 + d];
        *(float2*)(Xd + (d * 128 + r) * 2) = make_float2(v, v);
    }
    // ---- ||x||^2 in the reference's fp32 order: sequential a = a + (x*x) ----
    if (tid < 128) {
        const float* xp = Xp + tid * 68;
        float a = 0.0f;
        #pragma unroll
        for (int d = 0; d < 64; d++)
            a = __fadd_rn(a, __fmul_rn(xp[d], xp[d]));
        As[tid] = a;
    }
    // ---- ||c||^2 ----
    for (int k = tid; k < 256; k += 512) {
        float s = 0.0f;
        #pragma unroll
        for (int d = 0; d < 64; d++) { float v = Cs[d * 256 + k]; s = fmaf(v, v, s); }
        cc[k] = s;
    }
    __syncthreads();

    const int tx = tid & 31;   // -> column groups k = 4*tx + {0..3}, 128 + 4*tx + {0..3}
    const int ty = tid >> 5;   // -> rows r0 = ty*8 .. +7

    unsigned long long acc[8][4];
    #pragma unroll
    for (int i = 0; i < 8; i++)
        #pragma unroll
        for (int j = 0; j < 4; j++) acc[i][j] = 0ull;

    const ulonglong2* Xd2 = (const ulonglong2*)Xd;   // per d: 64 ull2 (128 float2)
    const ulonglong2* Cs2 = (const ulonglong2*)Cs;   // per d: 64 ull2 (256 floats)
    const int xbase = ty * 4;

    #pragma unroll 8
    for (int d = 0; d < 64; d++) {
        ulonglong2 x01 = Xd2[d * 64 + xbase + 0];   // dup(x[r0]), dup(x[r0+1])
        ulonglong2 x23 = Xd2[d * 64 + xbase + 1];
        ulonglong2 x45 = Xd2[d * 64 + xbase + 2];
        ulonglong2 x67 = Xd2[d * 64 + xbase + 3];
        ulonglong2 c0  = Cs2[d * 64 + tx];          // (c[4tx],c[4tx+1]) (c[4tx+2],c[4tx+3])
        ulonglong2 c1  = Cs2[d * 64 + 32 + tx];     // k + 128
        #define ROWFMA(i, xv) \
            acc[i][0] = ffma2(xv, c0.x, acc[i][0]); \
            acc[i][1] = ffma2(xv, c0.y, acc[i][1]); \
            acc[i][2] = ffma2(xv, c1.x, acc[i][2]); \
            acc[i][3] = ffma2(xv, c1.y, acc[i][3]);
        ROWFMA(0, x01.x) ROWFMA(1, x01.y)
        ROWFMA(2, x23.x) ROWFMA(3, x23.y)
        ROWFMA(4, x45.x) ROWFMA(5, x45.y)
        ROWFMA(6, x67.x) ROWFMA(7, x67.y)
        #undef ROWFMA
    }

    // ---- epilogue: emulate reference fp32 d2 = (A - 2 x.c) + ||c||^2,
    //      argmin over 256 with lowest-index tie-break (matches jnp.argmin) ----
    const float4* cc4 = (const float4*)cc;
    float4 ca = cc4[tx];
    float4 cb = cc4[tx + 32];
    const int r0 = ty * 8;

    #pragma unroll
    for (int i = 0; i < 8; i++) {
        const float A = As[r0 + i];
        // scanned in increasing k within this lane's set -> strict < keeps lowest k on ties
        float v  = rdist(A, f2lo(acc[i][0]), ca.x); int bi = 4 * tx;
        float s;
        s = rdist(A, f2hi(acc[i][0]), ca.y); if (s < v) { v = s; bi = 4 * tx + 1; }
        s = rdist(A, f2lo(acc[i][1]), ca.z); if (s < v) { v = s; bi = 4 * tx + 2; }
        s = rdist(A, f2hi(acc[i][1]), ca.w); if (s < v) { v = s; bi = 4 * tx + 3; }
        s = rdist(A, f2lo(acc[i][2]), cb.x); if (s < v) { v = s; bi = 128 + 4 * tx; }
        s = rdist(A, f2hi(acc[i][2]), cb.y); if (s < v) { v = s; bi = 128 + 4 * tx + 1; }
        s = rdist(A, f2lo(acc[i][3]), cb.z); if (s < v) { v = s; bi = 128 + 4 * tx + 2; }
        s = rdist(A, f2hi(acc[i][3]), cb.w); if (s < v) { v = s; bi = 128 + 4 * tx + 3; }

        #pragma unroll
        for (int off = 16; off > 0; off >>= 1) {
            float ov = __shfl_xor_sync(0xffffffffu, v, off);
            int   oi = __shfl_xor_sync(0xffffffffu, bi, off);
            if (ov < v || (ov == v && oi < bi)) { v = ov; bi = oi; }
        }

        int b = row0 + r0 + i;
        if (tx == 0) {
            codes_out[b * NBOOKS + n] = (float)bi;
            atomicAdd(&g_counts[n * KCODES + bi], 1.0f);
        }
        float xa = Xp[(r0 + i) * 68 + tx];
        float xb = Xp[(r0 + i) * 68 + tx + 32];
        float* dst = &g_dw[((size_t)(n * KCODES + bi)) * 64];
        atomicAdd(dst + tx, xa);
        atomicAdd(dst + tx + 32, xb);
    }
}

// EMA update + write count/weight/codebook outputs. 65536 threads: (n,k,d4).
__global__ void ema_kernel(const float* __restrict__ ec, const float* __restrict__ ew,
                           float* out)
{
    int i = blockIdx.x * blockDim.x + threadIdx.x;
    if (i >= NBOOKS * KCODES * 16) return;
    int d4 = i & 15;
    int nk = i >> 4;
    float nc = DECAY_F * ec[nk] + OMDECAY_F * g_counts[nk];
    float4 w  = *(const float4*)(ew + (size_t)nk * 64 + d4 * 4);
    float4 dv = *(const float4*)(g_dw + (size_t)nk * 64 + d4 * 4);
    float4 nw;
    nw.x = DECAY_F * w.x + OMDECAY_F * dv.x;
    nw.y = DECAY_F * w.y + OMDECAY_F * dv.y;
    nw.z = DECAY_F * w.z + OMDECAY_F * dv.z;
    nw.w = DECAY_F * w.w + OMDECAY_F * dv.w;
    float den = nc + EPS_F;
    float4 cbv;
    cbv.x = nw.x / den; cbv.y = nw.y / den; cbv.z = nw.z / den; cbv.w = nw.w / den;
    *(float4*)(out + OFF_W  + (size_t)nk * 64 + d4 * 4) = nw;
    *(float4*)(out + OFF_CB + (size_t)nk * 64 + d4 * 4) = cbv;
    if (d4 == 0) out[OFF_CNT + nk] = nc;
}

// recon gather: 8.4M threads, one float4 each
__global__ void recon_kernel(float* out)
{
    int i = blockIdx.x * blockDim.x + threadIdx.x;   // 0 .. B*16*16
    int d4 = i & 15;
    int bn = i >> 4;
    int n  = bn & 15;
    int b  = bn >> 4;
    int k  = (int)out[OFF_CODES + bn];
    float4 v = *(const float4*)(out + OFF_CB + ((size_t)(n * KCODES + k)) * 64 + d4 * 4);
    *(float4*)(out + OFF_RECON + (size_t)b * 1024 + n * 64 + d4 * 4) = v;
}

extern "C" void kernel_launch(void* const* d_in, const int* in_sizes, int n_in,
                              void* d_out, int out_size)
{
    const float* x   = (const float*)d_in[0];
    const float* cbk = (const float*)d_in[1];
    const float* ec  = (const float*)d_in[2];
    const float* ew  = (const float*)d_in[3];
    float* out = (float*)d_out;

    cudaFuncSetAttribute(assign_kernel,
                         cudaFuncAttributeMaxDynamicSharedMemorySize, SM_BYTES);

    zero_kernel<<<1024, 256>>>();
    dim3 grid(BATCH / 128, NBOOKS);
    assign_kernel<<<grid, 512, SM_BYTES>>>(x, cbk, out + OFF_CODES);
    ema_kernel<<<(NBOOKS * KCODES * 16) / 256, 256>>>(ec, ew, out);
    recon_kernel<<<(BATCH * NBOOKS * 16) / 256, 256>>>(out);
}

// round 5
// speedup vs baseline: 1.1773x; 1.1773x over previous
#include <cuda_runtime.h>
#include <stdint.h>

// Problem constants
#define BATCH   32768
#define NBOOKS  16
#define KCODES  256
#define DDIM    64
#define DECAY_F   0.99f
#define OMDECAY_F 0.010000000000000009f
#define EPS_F     1e-5f

// Output packing (tuple concatenated, f32):
//   codes [B,16] | recon [B,1024] | new_codebooks [16,256,64] | new_count [16,256] | new_weight [16,256,64]
#define OFF_CODES 0LL
#define OFF_RECON (32768LL * 16)
#define OFF_CB    (OFF_RECON + 32768LL * 1024)
#define OFF_CNT   (OFF_CB + 16LL * 256 * 64)
#define OFF_W     (OFF_CNT + 16LL * 256)

// Scratch
__device__ float g_counts[NBOOKS * KCODES];
__device__ float g_dw[NBOOKS * KCODES * DDIM];

// ---------------- shared memory layout (byte offsets) ----------------
// AH: uint4[64 frags][32 lanes]   tf32-high A fragments  : 32768 @ 0
// AL: uint4[64][32]               tf32-low  A fragments  : 32768 @ 32768
// BH: uint2[256 frags][32 lanes]  tf32-high B fragments  : 65536 @ 65536
// BL: uint2[256][32]              tf32-low  B fragments  : 65536 @ 131072
// (Xp: float[128][68] temporarily aliases BH/BL region during prologue)
// cc, As, cand_v, cand_i, codes
#define AH_OFF    0
#define AL_OFF    32768
#define BH_OFF    65536
#define BL_OFF    131072
#define XP_OFF    65536
#define CC_OFF    196608
#define AS_OFF    197632
#define CANDV_OFF 198144
#define CANDI_OFF 200192
#define CODES_OFF 202240
#define SM_BYTES  202752

// tf32 helpers
__device__ __forceinline__ uint32_t f2tf32(float x) {
    uint32_t r; asm("cvt.rna.tf32.f32 %0, %1;" : "=r"(r) : "f"(x)); return r;
}
__device__ __forceinline__ void split_tf32(float x, uint32_t& h, uint32_t& l) {
    h = f2tf32(x);
    l = f2tf32(__fsub_rn(x, __uint_as_float(h)));
}
// D += A*B, m16n8k8 tf32 (HMMA path, arch-portable: no 'a' target needed)
__device__ __forceinline__ void mma_tf32(float* d, const uint32_t* a, uint32_t b0, uint32_t b1) {
    asm volatile("mma.sync.aligned.m16n8k8.row.col.f32.tf32.tf32.f32 "
        "{%0,%1,%2,%3}, {%4,%5,%6,%7}, {%8,%9}, {%0,%1,%2,%3};"
        : "+f"(d[0]), "+f"(d[1]), "+f"(d[2]), "+f"(d[3])
        : "r"(a[0]), "r"(a[1]), "r"(a[2]), "r"(a[3]), "r"(b0), "r"(b1));
}
// Emulate reference fp32 elementwise: r = fl( fl(A - fl(2*dot)) + cc )
__device__ __forceinline__ float rdist(float A, float dot, float ccv) {
    return __fadd_rn(__fsub_rn(A, __fmul_rn(2.0f, dot)), ccv);
}

__global__ void zero_kernel() {
    int i = blockIdx.x * blockDim.x + threadIdx.x;
    if (i < NBOOKS * KCODES) g_counts[i] = 0.0f;
    if (i < NBOOKS * KCODES * DDIM) g_dw[i] = 0.0f;
}

// One CTA: book n = blockIdx.y, rows [blockIdx.x*128, +128). 512 threads.
// 3xTF32 split GEMM on mma.sync (register accumulators), exact-argmin epilogue.
__global__ void __launch_bounds__(512, 1)
assign_kernel(const float* __restrict__ x, const float* __restrict__ cbk,
              float* codes_out)
{
    extern __shared__ char sm[];
    float* Xp = (float*)(sm + XP_OFF);
    float* cc = (float*)(sm + CC_OFF);
    float* As = (float*)(sm + AS_OFF);
    float* cand_v = (float*)(sm + CANDV_OFF);
    int*   cand_i = (int*)(sm + CANDI_OFF);
    int*   codes_sm = (int*)(sm + CODES_OFF);

    const int tid = threadIdx.x;
    const int wid = tid >> 5;
    const int lid = tid & 31;
    const int g = lid >> 2;         // groupID
    const int q = lid & 3;          // thread-in-group
    const int n = blockIdx.y;
    const int row0 = blockIdx.x * 128;

    // ---- phase 1: stage x tile (coalesced gmem -> Xp, stride 68) ----
    for (int t = tid; t < 2048; t += 512) {
        int r = t >> 4, c4 = t & 15;
        float4 v = *(const float4*)(x + (size_t)(row0 + r) * 1024 + n * 64 + c4 * 4);
        *(float4*)(Xp + r * 68 + c4 * 4) = v;
    }
    __syncthreads();

    // ---- phase 2a: ||x||^2 in the reference's exact fp32 order (bit-critical) ----
    if (tid < 128) {
        const float* xp = Xp + tid * 68;
        float a = 0.0f;
        #pragma unroll
        for (int d = 0; d < 64; d++)
            a = __fadd_rn(a, __fmul_rn(xp[d], xp[d]));
        As[tid] = a;
    }
    // ---- phase 2b: build A fragments (64 frags; warp w -> frags 4w..4w+3) ----
    #pragma unroll
    for (int i = 0; i < 4; i++) {
        int f = wid * 4 + i;            // f = mt*8 + ks
        int mt = f >> 3, ks = f & 7;
        int r1 = mt * 16 + g;           // rows g, g+8 of this m16 tile
        int c1 = ks * 8 + q;            // cols q, q+4 of this k8 slice
        float a0 = Xp[r1 * 68 + c1];
        float a1 = Xp[(r1 + 8) * 68 + c1];
        float a2 = Xp[r1 * 68 + c1 + 4];
        float a3 = Xp[(r1 + 8) * 68 + c1 + 4];
        uint4 h, l;
        split_tf32(a0, h.x, l.x); split_tf32(a1, h.y, l.y);
        split_tf32(a2, h.z, l.z); split_tf32(a3, h.w, l.w);
        *(uint4*)(sm + AH_OFF + (f * 32 + lid) * 16) = h;
        *(uint4*)(sm + AL_OFF + (f * 32 + lid) * 16) = l;
    }
    // ---- phase 2c: cc = ||c_k||^2 (gmem, coalesced) ----
    #pragma unroll
    for (int it = 0; it < 16; it++) {
        int k = wid * 16 + it;
        float2 cv = *(const float2*)(cbk + ((size_t)(n * 256 + k)) * 64 + 2 * lid);
        float p = fmaf(cv.x, cv.x, cv.y * cv.y);
        #pragma unroll
        for (int off = 16; off > 0; off >>= 1)
            p += __shfl_xor_sync(0xffffffffu, p, off);
        if (lid == 0) cc[k] = p;
    }
    __syncthreads();

    // ---- phase 3: build B fragments (256 frags; warp w -> 16), overwrites Xp ----
    #pragma unroll
    for (int it = 0; it < 16; it++) {
        int f = wid * 16 + it;          // f = nt*8 + ks
        int nt = f >> 3, ks = f & 7;
        int nn = nt * 8 + g;            // code row
        int k1 = ks * 8 + q;
        const float* cr = cbk + ((size_t)(n * 256 + nn)) * 64;
        float b0 = cr[k1];
        float b1 = cr[k1 + 4];
        uint2 h, l;
        split_tf32(b0, h.x, l.x); split_tf32(b1, h.y, l.y);
        *(uint2*)(sm + BH_OFF + (f * 32 + lid) * 8) = h;
        *(uint2*)(sm + BL_OFF + (f * 32 + lid) * 8) = l;
    }
    __syncthreads();

    // ---- mainloop: warp (mw, nw) computes 32x64; acc in registers ----
    const int mw = wid & 3;             // m-block: rows mw*32..+31 (mtiles 2mw, 2mw+1)
    const int nw = wid >> 2;            // n-block: cols nw*64..+63 (ntiles 8nw..8nw+7)
    float acc[2][8][4];
    #pragma unroll
    for (int mt = 0; mt < 2; mt++)
        #pragma unroll
        for (int nt = 0; nt < 8; nt++)
            #pragma unroll
            for (int e = 0; e < 4; e++) acc[mt][nt][e] = 0.0f;

    #pragma unroll
    for (int ks = 0; ks < 8; ks++) {
        uint4 ah0 = *(const uint4*)(sm + AH_OFF + (((2 * mw) * 8 + ks) * 32 + lid) * 16);
        uint4 al0 = *(const uint4*)(sm + AL_OFF + (((2 * mw) * 8 + ks) * 32 + lid) * 16);
        uint4 ah1 = *(const uint4*)(sm + AH_OFF + (((2 * mw + 1) * 8 + ks) * 32 + lid) * 16);
        uint4 al1 = *(const uint4*)(sm + AL_OFF + (((2 * mw + 1) * 8 + ks) * 32 + lid) * 16);
        #pragma unroll
        for (int nt = 0; nt < 8; nt++) {
            int f = (8 * nw + nt) * 8 + ks;
            uint2 bh = *(const uint2*)(sm + BH_OFF + (f * 32 + lid) * 8);
            uint2 bl = *(const uint2*)(sm + BL_OFF + (f * 32 + lid) * 8);
            mma_tf32(acc[0][nt], (const uint32_t*)&ah0, bl.x, bl.y);
            mma_tf32(acc[0][nt], (const uint32_t*)&al0, bh.x, bh.y);
            mma_tf32(acc[0][nt], (const uint32_t*)&ah0, bh.x, bh.y);
            mma_tf32(acc[1][nt], (const uint32_t*)&ah1, bl.x, bl.y);
            mma_tf32(acc[1][nt], (const uint32_t*)&al1, bh.x, bh.y);
            mma_tf32(acc[1][nt], (const uint32_t*)&ah1, bh.x, bh.y);
        }
    }

    // ---- epilogue: rdist + argmin (lowest-index ties, matching jnp.argmin) ----
    float ccv[16];
    #pragma unroll
    for (int nt = 0; nt < 8; nt++) {
        float2 cp = *(const float2*)(cc + 64 * nw + 8 * nt + 2 * q);
        ccv[2 * nt] = cp.x; ccv[2 * nt + 1] = cp.y;
    }
    #pragma unroll
    for (int mt = 0; mt < 2; mt++) {
        #pragma unroll
        for (int rr = 0; rr < 2; rr++) {
            int lrow = mw * 32 + mt * 16 + rr * 8 + g;
            float A = As[lrow];
            float v = 0.0f; int bi = -1;
            #pragma unroll
            for (int nt = 0; nt < 8; nt++) {
                #pragma unroll
                for (int e = 0; e < 2; e++) {
                    float s = rdist(A, acc[mt][nt][rr * 2 + e], ccv[2 * nt + e]);
                    int ci = 64 * nw + 8 * nt + 2 * q + e;
                    if (bi < 0 || s < v) { v = s; bi = ci; }
                }
            }
            // reduce across the quad (lanes sharing g)
            #pragma unroll
            for (int off = 1; off <= 2; off <<= 1) {
                float ov = __shfl_xor_sync(0xffffffffu, v, off);
                int   oi = __shfl_xor_sync(0xffffffffu, bi, off);
                if (ov < v || (ov == v && oi < bi)) { v = ov; bi = oi; }
            }
            if (q == 0) {
                cand_v[lrow * 4 + nw] = v;
                cand_i[lrow * 4 + nw] = bi;
            }
        }
    }
    __syncthreads();

    // ---- combine 4 n-block candidates per row (ascending), write codes/counts ----
    if (tid < 128) {
        float v = cand_v[tid * 4];
        int bi = cand_i[tid * 4];
        #pragma unroll
        for (int p = 1; p < 4; p++) {
            float s = cand_v[tid * 4 + p];
            int si = cand_i[tid * 4 + p];
            if (s < v) { v = s; bi = si; }
        }
        codes_sm[tid] = bi;
        codes_out[(size_t)(row0 + tid) * NBOOKS + n] = (float)bi;
        atomicAdd(&g_counts[n * KCODES + bi], 1.0f);
    }
    __syncthreads();

    // ---- dw scatter: warp per 8 rows, x re-read from gmem (L2 hit, coalesced) ----
    {
        const int rb = wid * 8;
        #pragma unroll
        for (int i = 0; i < 8; i++) {
            int r = rb + i;
            int bi = codes_sm[r];
            const float* xr = x + (size_t)(row0 + r) * 1024 + n * 64;
            float xa = xr[lid];
            float xb = xr[lid + 32];
            float* dst = &g_dw[((size_t)(n * KCODES + bi)) * 64];
            atomicAdd(dst + lid, xa);
            atomicAdd(dst + lid + 32, xb);
        }
    }
}

// EMA update + write count/weight/codebook outputs.
__global__ void ema_kernel(const float* __restrict__ ec, const float* __restrict__ ew,
                           float* out)
{
    int i = blockIdx.x * blockDim.x + threadIdx.x;
    if (i >= NBOOKS * KCODES * 16) return;
    int d4 = i & 15;
    int nk = i >> 4;
    float nc = DECAY_F * ec[nk] + OMDECAY_F * g_counts[nk];
    float4 w  = *(const float4*)(ew + (size_t)nk * 64 + d4 * 4);
    float4 dv = *(const float4*)(g_dw + (size_t)nk * 64 + d4 * 4);
    float4 nw;
    nw.x = DECAY_F * w.x + OMDECAY_F * dv.x;
    nw.y = DECAY_F * w.y + OMDECAY_F * dv.y;
    nw.z = DECAY_F * w.z + OMDECAY_F * dv.z;
    nw.w = DECAY_F * w.w + OMDECAY_F * dv.w;
    float den = nc + EPS_F;
    float4 cbv;
    cbv.x = nw.x / den; cbv.y = nw.y / den; cbv.z = nw.z / den; cbv.w = nw.w / den;
    *(float4*)(out + OFF_W  + (size_t)nk * 64 + d4 * 4) = nw;
    *(float4*)(out + OFF_CB + (size_t)nk * 64 + d4 * 4) = cbv;
    if (d4 == 0) out[OFF_CNT + nk] = nc;
}

// recon gather
__global__ void recon_kernel(float* out)
{
    int i = blockIdx.x * blockDim.x + threadIdx.x;
    int d4 = i & 15;
    int bn = i >> 4;
    int n  = bn & 15;
    int b  = bn >> 4;
    int k  = (int)out[OFF_CODES + bn];
    float4 v = *(const float4*)(out + OFF_CB + ((size_t)(n * KCODES + k)) * 64 + d4 * 4);
    *(float4*)(out + OFF_RECON + (size_t)b * 1024 + n * 64 + d4 * 4) = v;
}

extern "C" void kernel_launch(void* const* d_in, const int* in_sizes, int n_in,
                              void* d_out, int out_size)
{
    const float* x   = (const float*)d_in[0];
    const float* cbk = (const float*)d_in[1];
    const float* ec  = (const float*)d_in[2];
    const float* ew  = (const float*)d_in[3];
    float* out = (float*)d_out;

    cudaFuncSetAttribute(assign_kernel,
                         cudaFuncAttributeMaxDynamicSharedMemorySize, SM_BYTES);

    zero_kernel<<<1024, 256>>>();
    dim3 grid(BATCH / 128, NBOOKS);
    assign_kernel<<<grid, 512, SM_BYTES>>>(x, cbk, out + OFF_CODES);
    ema_kernel<<<(NBOOKS * KCODES * 16) / 256, 256>>>(ec, ew, out);
    recon_kernel<<<(BATCH * NBOOKS * 16) / 256, 256>>>(out);
}

// round 6
// speedup vs baseline: 1.6477x; 1.3996x over previous
#include <cuda_runtime.h>
#include <cuda_fp16.h>
#include <stdint.h>

// Problem constants
#define BATCH   32768
#define NBOOKS  16
#define KCODES  256
#define DDIM    64
#define DECAY_F   0.99f
#define OMDECAY_F 0.010000000000000009f
#define EPS_F     1e-5f

// Output packing (tuple concatenated, f32):
//   codes [B,16] | recon [B,1024] | new_codebooks [16,256,64] | new_count [16,256] | new_weight [16,256,64]
#define OFF_CODES 0LL
#define OFF_RECON (32768LL * 16)
#define OFF_CB    (OFF_RECON + 32768LL * 1024)
#define OFF_CNT   (OFF_CB + 16LL * 256 * 64)
#define OFF_W     (OFF_CNT + 16LL * 256)

// Codebook pre-scale 2^6 (exact; undone by *2^-6 on accumulator) keeps
// fp16 split-low parts in normal range.
#define CSCALE   64.0f
#define CUNSCALE 0.015625f

// Scratch
__device__ float g_counts[NBOOKS * KCODES];
__device__ float g_dw[NBOOKS * KCODES * DDIM];

// ---------------- shared memory layout (byte offsets) ----------------
// AH: uint4[32 frags][32 lanes]  fp16-high A frags (m16k16) : 16384 @ 0
// AL: uint4[32][32]              fp16-low  A frags          : 16384 @ 16384
// BH: uint2[128 frags][32 lanes] fp16-high B frags (k16n8)  : 32768 @ 32768
// BL: uint2[128][32]             fp16-low  B frags          : 32768 @ 65536
// Xp: float[128][68]                                        : 34816 @ 98304
// cc, As, cand_v, cand_i, codes
#define AH_OFF    0
#define AL_OFF    16384
#define BH_OFF    32768
#define BL_OFF    65536
#define XP_OFF    98304
#define CC_OFF    133120
#define AS_OFF    134144
#define CANDV_OFF 134656
#define CANDI_OFF 136704
#define CODES_OFF 138752
#define SM_BYTES  139264

// fp16 2-way split: h = rn(v), l = rn(v - h). Residual ~2^-23 |v|.
__device__ __forceinline__ void split_h(float v, __half& h, __half& l) {
    h = __float2half_rn(v);
    l = __float2half_rn(__fsub_rn(v, __half2float(h)));
}
__device__ __forceinline__ uint32_t pack2(__half lo, __half hi) {
    __half2 p = __halves2half2(lo, hi);
    return *(uint32_t*)&p;
}
// D += A*B, m16n8k16 fp16 -> f32 (arch-portable HMMA, no 'a' target needed)
__device__ __forceinline__ void mma_f16(float* d, const uint32_t* a, uint32_t b0, uint32_t b1) {
    asm volatile("mma.sync.aligned.m16n8k16.row.col.f32.f16.f16.f32 "
        "{%0,%1,%2,%3}, {%4,%5,%6,%7}, {%8,%9}, {%0,%1,%2,%3};"
        : "+f"(d[0]), "+f"(d[1]), "+f"(d[2]), "+f"(d[3])
        : "r"(a[0]), "r"(a[1]), "r"(a[2]), "r"(a[3]), "r"(b0), "r"(b1));
}
// Emulate reference fp32 elementwise: r = fl( fl(A - fl(2*dot)) + cc )
__device__ __forceinline__ float rdist(float A, float dot, float ccv) {
    return __fadd_rn(__fsub_rn(A, __fmul_rn(2.0f, dot)), ccv);
}

__global__ void zero_kernel() {
    int i = blockIdx.x * blockDim.x + threadIdx.x;
    if (i < NBOOKS * KCODES) g_counts[i] = 0.0f;
    if (i < NBOOKS * KCODES * DDIM) g_dw[i] = 0.0f;
}

// One CTA: book n = blockIdx.y, rows [blockIdx.x*128, +128). 512 threads.
// fp16 2-split GEMM (3 products: hh + hl + lh) on mma.sync m16n8k16.
__global__ void __launch_bounds__(512, 1)
assign_kernel(const float* __restrict__ x, const float* __restrict__ cbk,
              float* codes_out)
{
    extern __shared__ char sm[];
    float* Xp = (float*)(sm + XP_OFF);
    float* cc = (float*)(sm + CC_OFF);
    float* As = (float*)(sm + AS_OFF);
    float* cand_v = (float*)(sm + CANDV_OFF);
    int*   cand_i = (int*)(sm + CANDI_OFF);
    int*   codes_sm = (int*)(sm + CODES_OFF);

    const int tid = threadIdx.x;
    const int wid = tid >> 5;
    const int lid = tid & 31;
    const int g = lid >> 2;         // groupID
    const int q = lid & 3;          // thread-in-group
    const int n = blockIdx.y;
    const int row0 = blockIdx.x * 128;

    // ---- phase 1: stage x tile (coalesced gmem -> Xp, stride 68) ----
    for (int t = tid; t < 2048; t += 512) {
        int r = t >> 4, c4 = t & 15;
        float4 v = *(const float4*)(x + (size_t)(row0 + r) * 1024 + n * 64 + c4 * 4);
        *(float4*)(Xp + r * 68 + c4 * 4) = v;
    }
    __syncthreads();

    // ---- phase 2a: ||x||^2 in the reference's exact fp32 order (bit-critical) ----
    if (tid < 128) {
        const float* xp = Xp + tid * 68;
        float a = 0.0f;
        #pragma unroll
        for (int d = 0; d < 64; d++)
            a = __fadd_rn(a, __fmul_rn(xp[d], xp[d]));
        As[tid] = a;
    }
    // ---- phase 2b: build A fragments (32 frags = mt*4+ks; 2 per warp) ----
    #pragma unroll
    for (int i = 0; i < 2; i++) {
        int f = wid * 2 + i;
        int mt = f >> 2, ks = f & 3;
        int r1 = mt * 16 + g;               // rows g, g+8
        int c0 = ks * 16 + 2 * q;           // cols 2q,2q+1 and +8,+9
        float2 p0 = *(const float2*)(Xp + r1 * 68 + c0);
        float2 p1 = *(const float2*)(Xp + (r1 + 8) * 68 + c0);
        float2 p2 = *(const float2*)(Xp + r1 * 68 + c0 + 8);
        float2 p3 = *(const float2*)(Xp + (r1 + 8) * 68 + c0 + 8);
        __half h0a, l0a, h0b, l0b, h1a, l1a, h1b, l1b;
        __half h2a, l2a, h2b, l2b, h3a, l3a, h3b, l3b;
        split_h(p0.x, h0a, l0a); split_h(p0.y, h0b, l0b);
        split_h(p1.x, h1a, l1a); split_h(p1.y, h1b, l1b);
        split_h(p2.x, h2a, l2a); split_h(p2.y, h2b, l2b);
        split_h(p3.x, h3a, l3a); split_h(p3.y, h3b, l3b);
        uint4 H = make_uint4(pack2(h0a, h0b), pack2(h1a, h1b), pack2(h2a, h2b), pack2(h3a, h3b));
        uint4 L = make_uint4(pack2(l0a, l0b), pack2(l1a, l1b), pack2(l2a, l2b), pack2(l3a, l3b));
        *(uint4*)(sm + AH_OFF + (f * 32 + lid) * 16) = H;
        *(uint4*)(sm + AL_OFF + (f * 32 + lid) * 16) = L;
    }
    // ---- phase 2c: cc = ||c_k||^2 (unscaled, fp32, coalesced) ----
    #pragma unroll
    for (int it = 0; it < 16; it++) {
        int k = wid * 16 + it;
        float2 cv = *(const float2*)(cbk + ((size_t)(n * 256 + k)) * 64 + 2 * lid);
        float p = fmaf(cv.x, cv.x, cv.y * cv.y);
        #pragma unroll
        for (int off = 16; off > 0; off >>= 1)
            p += __shfl_xor_sync(0xffffffffu, p, off);
        if (lid == 0) cc[k] = p;
    }
    // ---- phase 3: build B fragments (128 frags = nt*4+ks; 8 per warp), c *= 64 ----
    #pragma unroll
    for (int it = 0; it < 8; it++) {
        int f = wid * 8 + it;
        int nt = f >> 2, ks = f & 3;
        int code = nt * 8 + g;
        int k0 = ks * 16 + 2 * q;
        const float* cr = cbk + ((size_t)(n * 256 + code)) * 64;
        float2 u0 = *(const float2*)(cr + k0);
        float2 u1 = *(const float2*)(cr + k0 + 8);
        __half h0a, l0a, h0b, l0b, h1a, l1a, h1b, l1b;
        split_h(u0.x * CSCALE, h0a, l0a); split_h(u0.y * CSCALE, h0b, l0b);
        split_h(u1.x * CSCALE, h1a, l1a); split_h(u1.y * CSCALE, h1b, l1b);
        uint2 H = make_uint2(pack2(h0a, h0b), pack2(h1a, h1b));
        uint2 L = make_uint2(pack2(l0a, l0b), pack2(l1a, l1b));
        *(uint2*)(sm + BH_OFF + (f * 32 + lid) * 8) = H;
        *(uint2*)(sm + BL_OFF + (f * 32 + lid) * 8) = L;
    }
    __syncthreads();

    // ---- mainloop: warp (mw, nw) computes 32x64; acc in registers ----
    const int mw = wid & 3;             // rows mw*32..+31 (mtiles 2mw, 2mw+1)
    const int nw = wid >> 2;            // cols nw*64..+63 (ntiles 8nw..8nw+7)
    float acc[2][8][4];
    #pragma unroll
    for (int mt = 0; mt < 2; mt++)
        #pragma unroll
        for (int nt = 0; nt < 8; nt++)
            #pragma unroll
            for (int e = 0; e < 4; e++) acc[mt][nt][e] = 0.0f;

    #pragma unroll
    for (int ks = 0; ks < 4; ks++) {
        uint4 ah0 = *(const uint4*)(sm + AH_OFF + (((2 * mw) * 4 + ks) * 32 + lid) * 16);
        uint4 al0 = *(const uint4*)(sm + AL_OFF + (((2 * mw) * 4 + ks) * 32 + lid) * 16);
        uint4 ah1 = *(const uint4*)(sm + AH_OFF + (((2 * mw + 1) * 4 + ks) * 32 + lid) * 16);
        uint4 al1 = *(const uint4*)(sm + AL_OFF + (((2 * mw + 1) * 4 + ks) * 32 + lid) * 16);
        #pragma unroll
        for (int nt = 0; nt < 8; nt++) {
            int f = (8 * nw + nt) * 4 + ks;
            uint2 bh = *(const uint2*)(sm + BH_OFF + (f * 32 + lid) * 8);
            uint2 bl = *(const uint2*)(sm + BL_OFF + (f * 32 + lid) * 8);
            mma_f16(acc[0][nt], (const uint32_t*)&ah0, bl.x, bl.y);   // h*l
            mma_f16(acc[0][nt], (const uint32_t*)&al0, bh.x, bh.y);   // l*h
            mma_f16(acc[0][nt], (const uint32_t*)&ah0, bh.x, bh.y);   // h*h
            mma_f16(acc[1][nt], (const uint32_t*)&ah1, bl.x, bl.y);
            mma_f16(acc[1][nt], (const uint32_t*)&al1, bh.x, bh.y);
            mma_f16(acc[1][nt], (const uint32_t*)&ah1, bh.x, bh.y);
        }
    }

    // ---- epilogue: rdist + argmin (lowest-index ties, matching jnp.argmin) ----
    float ccv[16];
    #pragma unroll
    for (int nt = 0; nt < 8; nt++) {
        float2 cp = *(const float2*)(cc + 64 * nw + 8 * nt + 2 * q);
        ccv[2 * nt] = cp.x; ccv[2 * nt + 1] = cp.y;
    }
    #pragma unroll
    for (int mt = 0; mt < 2; mt++) {
        #pragma unroll
        for (int rr = 0; rr < 2; rr++) {
            int lrow = mw * 32 + mt * 16 + rr * 8 + g;
            float A = As[lrow];
            float v = 0.0f; int bi = -1;
            #pragma unroll
            for (int nt = 0; nt < 8; nt++) {
                #pragma unroll
                for (int e = 0; e < 2; e++) {
                    float dot = acc[mt][nt][rr * 2 + e] * CUNSCALE;   // exact /64
                    float s = rdist(A, dot, ccv[2 * nt + e]);
                    int ci = 64 * nw + 8 * nt + 2 * q + e;
                    if (bi < 0 || s < v) { v = s; bi = ci; }
                }
            }
            // reduce across the quad (lanes sharing g)
            #pragma unroll
            for (int off = 1; off <= 2; off <<= 1) {
                float ov = __shfl_xor_sync(0xffffffffu, v, off);
                int   oi = __shfl_xor_sync(0xffffffffu, bi, off);
                if (ov < v || (ov == v && oi < bi)) { v = ov; bi = oi; }
            }
            if (q == 0) {
                cand_v[lrow * 4 + nw] = v;
                cand_i[lrow * 4 + nw] = bi;
            }
        }
    }
    __syncthreads();

    // ---- combine 4 n-block candidates per row (ascending), write codes/counts ----
    if (tid < 128) {
        float v = cand_v[tid * 4];
        int bi = cand_i[tid * 4];
        #pragma unroll
        for (int p = 1; p < 4; p++) {
            float s = cand_v[tid * 4 + p];
            int si = cand_i[tid * 4 + p];
            if (s < v) { v = s; bi = si; }
        }
        codes_sm[tid] = bi;
        codes_out[(size_t)(row0 + tid) * NBOOKS + n] = (float)bi;
        atomicAdd(&g_counts[n * KCODES + bi], 1.0f);
    }
    __syncthreads();

    // ---- dw scatter: warp per 8 rows, x re-read from Xp ----
    {
        const int rb = wid * 8;
        #pragma unroll
        for (int i = 0; i < 8; i++) {
            int r = rb + i;
            int bi = codes_sm[r];
            float xa = Xp[r * 68 + lid];
            float xb = Xp[r * 68 + lid + 32];
            float* dst = &g_dw[((size_t)(n * KCODES + bi)) * 64];
            atomicAdd(dst + lid, xa);
            atomicAdd(dst + lid + 32, xb);
        }
    }
}

// EMA update + write count/weight/codebook outputs.
__global__ void ema_kernel(const float* __restrict__ ec, const float* __restrict__ ew,
                           float* out)
{
    int i = blockIdx.x * blockDim.x + threadIdx.x;
    if (i >= NBOOKS * KCODES * 16) return;
    int d4 = i & 15;
    int nk = i >> 4;
    float nc = DECAY_F * ec[nk] + OMDECAY_F * g_counts[nk];
    float4 w  = *(const float4*)(ew + (size_t)nk * 64 + d4 * 4);
    float4 dv = *(const float4*)(g_dw + (size_t)nk * 64 + d4 * 4);
    float4 nw;
    nw.x = DECAY_F * w.x + OMDECAY_F * dv.x;
    nw.y = DECAY_F * w.y + OMDECAY_F * dv.y;
    nw.z = DECAY_F * w.z + OMDECAY_F * dv.z;
    nw.w = DECAY_F * w.w + OMDECAY_F * dv.w;
    float den = nc + EPS_F;
    float4 cbv;
    cbv.x = nw.x / den; cbv.y = nw.y / den; cbv.z = nw.z / den; cbv.w = nw.w / den;
    *(float4*)(out + OFF_W  + (size_t)nk * 64 + d4 * 4) = nw;
    *(float4*)(out + OFF_CB + (size_t)nk * 64 + d4 * 4) = cbv;
    if (d4 == 0) out[OFF_CNT + nk] = nc;
}

// recon gather
__global__ void recon_kernel(float* out)
{
    int i = blockIdx.x * blockDim.x + threadIdx.x;
    int d4 = i & 15;
    int bn = i >> 4;
    int n  = bn & 15;
    int b  = bn >> 4;
    int k  = (int)out[OFF_CODES + bn];
    float4 v = *(const float4*)(out + OFF_CB + ((size_t)(n * KCODES + k)) * 64 + d4 * 4);
    *(float4*)(out + OFF_RECON + (size_t)b * 1024 + n * 64 + d4 * 4) = v;
}

extern "C" void kernel_launch(void* const* d_in, const int* in_sizes, int n_in,
                              void* d_out, int out_size)
{
    const float* x   = (const float*)d_in[0];
    const float* cbk = (const float*)d_in[1];
    const float* ec  = (const float*)d_in[2];
    const float* ew  = (const float*)d_in[3];
    float* out = (float*)d_out;

    cudaFuncSetAttribute(assign_kernel,
                         cudaFuncAttributeMaxDynamicSharedMemorySize, SM_BYTES);

    zero_kernel<<<1024, 256>>>();
    dim3 grid(BATCH / 128, NBOOKS);
    assign_kernel<<<grid, 512, SM_BYTES>>>(x, cbk, out + OFF_CODES);
    ema_kernel<<<(NBOOKS * KCODES * 16) / 256, 256>>>(ec, ew, out);
    recon_kernel<<<(BATCH * NBOOKS * 16) / 256, 256>>>(out);
}

// round 8
// speedup vs baseline: 2.2635x; 1.3738x over previous
#include <cuda_runtime.h>
#include <cuda_fp16.h>
#include <stdint.h>

// Problem constants
#define BATCH   32768
#define NBOOKS  16
#define KCODES  256
#define DDIM    64
#define DECAY_F   0.99f
#define OMDECAY_F 0.010000000000000009f
#define EPS_F     1e-5f

// Output packing (tuple concatenated, f32):
//   codes [B,16] | recon [B,1024] | new_codebooks [16,256,64] | new_count [16,256] | new_weight [16,256,64]
#define OFF_CODES 0LL
#define OFF_RECON (32768LL * 16)
#define OFF_CB    (OFF_RECON + 32768LL * 1024)
#define OFF_CNT   (OFF_CB + 16LL * 256 * 64)
#define OFF_W     (OFF_CNT + 16LL * 256)

// Codebook pre-scale 2^6 (exact; undone by *2^-6) keeps fp16 lows normal.
#define CSCALE   64.0f
#define CUNSCALE 0.015625f

// Scratch (device globals: no cudaMalloc allowed)
__device__ float g_counts[NBOOKS * KCODES];
__device__ float g_dw[NBOOKS * KCODES * DDIM];
__device__ uint2 g_bfH[NBOOKS * 128 * 32];   // fp16-high B fragments (k16n8)
__device__ uint2 g_bfL[NBOOKS * 128 * 32];   // fp16-low  B fragments
__device__ float g_cc[NBOOKS * KCODES];      // ||c_k||^2

// ---------------- assign smem layout (byte offsets), 64-row tile ----------------
#define XP_OFF    0          // float[64][68]  = 17408
#define AH_OFF    17408      // uint4[16][32]  = 8192
#define AL_OFF    25600      // uint4[16][32]  = 8192
#define CC_OFF    33792      // float[256]     = 1024
#define AS_OFF    34816      // float[64]      = 256
#define CANDV_OFF 35072      // float[64*4]    = 1024
#define CANDI_OFF 36096      // int[64*4]      = 1024
#define CODES_OFF 37120      // int[64]        = 256
#define SM_BYTES  37376

// fp16 2-way split: h = rn(v), l = rn(v - h).
__device__ __forceinline__ void split_h(float v, __half& h, __half& l) {
    h = __float2half_rn(v);
    l = __float2half_rn(__fsub_rn(v, __half2float(h)));
}
__device__ __forceinline__ uint32_t pack2(__half lo, __half hi) {
    __half2 p = __halves2half2(lo, hi);
    return *(uint32_t*)&p;
}
// D += A*B, m16n8k16 fp16 -> f32 (arch-portable HMMA)
__device__ __forceinline__ void mma_f16(float* d, const uint32_t* a, uint32_t b0, uint32_t b1) {
    asm volatile("mma.sync.aligned.m16n8k16.row.col.f32.f16.f16.f32 "
        "{%0,%1,%2,%3}, {%4,%5,%6,%7}, {%8,%9}, {%0,%1,%2,%3};"
        : "+f"(d[0]), "+f"(d[1]), "+f"(d[2]), "+f"(d[3])
        : "r"(a[0]), "r"(a[1]), "r"(a[2]), "r"(a[3]), "r"(b0), "r"(b1));
}
// Emulate reference fp32 elementwise: r = fl( fl(A - fl(2*dot)) + cc )
__device__ __forceinline__ float rdist(float A, float dot, float ccv) {
    return __fadd_rn(__fsub_rn(A, __fmul_rn(2.0f, dot)), ccv);
}

// ---- prep: per book, build B fragments + cc, zero counts/dw. grid=(16), 256 thr ----
__global__ void prep_kernel(const float* __restrict__ cbk)
{
    const int n = blockIdx.x;
    const int tid = threadIdx.x;
    const int wid = tid >> 5;
    const int lid = tid & 31;
    const int g = lid >> 2, q = lid & 3;

    // zero counts + dw
    if (tid < 256) g_counts[n * 256 + tid] = 0.0f;
    float4 z4 = make_float4(0.f, 0.f, 0.f, 0.f);
    #pragma unroll
    for (int i = 0; i < 16; i++)
        *(float4*)(g_dw + (size_t)n * 16384 + (i * 256 + tid) * 4) = z4;

    // B fragments: f = nt_global*4 + ks, 128 frags, 16 per warp
    #pragma unroll
    for (int it = 0; it < 16; it++) {
        int f = wid * 16 + it;
        int ntg = f >> 2, ks = f & 3;
        int code = ntg * 8 + g;
        int k0 = ks * 16 + 2 * q;
        const float* cr = cbk + ((size_t)(n * 256 + code)) * 64;
        float2 u0 = *(const float2*)(cr + k0);
        float2 u1 = *(const float2*)(cr + k0 + 8);
        __half h0a, l0a, h0b, l0b, h1a, l1a, h1b, l1b;
        split_h(u0.x * CSCALE, h0a, l0a); split_h(u0.y * CSCALE, h0b, l0b);
        split_h(u1.x * CSCALE, h1a, l1a); split_h(u1.y * CSCALE, h1b, l1b);
        g_bfH[((size_t)n * 128 + f) * 32 + lid] = make_uint2(pack2(h0a, h0b), pack2(h1a, h1b));
        g_bfL[((size_t)n * 128 + f) * 32 + lid] = make_uint2(pack2(l0a, l0b), pack2(l1a, l1b));
    }
    // cc, same float order as the passing rounds (per-lane fmaf + butterfly)
    #pragma unroll
    for (int it = 0; it < 32; it++) {
        int k = wid * 32 + it;
        float2 cv = *(const float2*)(cbk + ((size_t)(n * 256 + k)) * 64 + 2 * lid);
        float p = fmaf(cv.x, cv.x, cv.y * cv.y);
        #pragma unroll
        for (int off = 16; off > 0; off >>= 1)
            p += __shfl_xor_sync(0xffffffffu, p, off);
        if (lid == 0) g_cc[n * 256 + k] = p;
    }
}

// ---- assign: CTA = 64 rows x book, 256 threads, 2 CTAs/SM ----
__global__ void __launch_bounds__(256, 2)
assign_kernel(const float* __restrict__ x, float* codes_out)
{
    extern __shared__ char sm[];
    float* Xp = (float*)(sm + XP_OFF);
    float* cc = (float*)(sm + CC_OFF);
    float* As = (float*)(sm + AS_OFF);
    float* cand_v = (float*)(sm + CANDV_OFF);
    int*   cand_i = (int*)(sm + CANDI_OFF);
    int*   codes_sm = (int*)(sm + CODES_OFF);

    const int tid = threadIdx.x;
    const int wid = tid >> 5;
    const int lid = tid & 31;
    const int g = lid >> 2;
    const int q = lid & 3;
    const int n = blockIdx.y;
    const int row0 = blockIdx.x * 64;

    // ---- stage x tile (coalesced) ----
    for (int t = tid; t < 1024; t += 256) {
        int r = t >> 4, c4 = t & 15;
        float4 v = *(const float4*)(x + (size_t)(row0 + r) * 1024 + n * 64 + c4 * 4);
        *(float4*)(Xp + r * 68 + c4 * 4) = v;
    }
    __syncthreads();

    // ---- ||x||^2 in the reference's exact fp32 order (bit-critical) ----
    if (tid < 64) {
        const float* xp = Xp + tid * 68;
        float a = 0.0f;
        #pragma unroll
        for (int d = 0; d < 64; d++)
            a = __fadd_rn(a, __fmul_rn(xp[d], xp[d]));
        As[tid] = a;
    }
    // ---- cc from global ----
    cc[tid] = g_cc[n * 256 + tid];
    // ---- A fragments: 16 frags = mt*4+ks, 2 per warp ----
    #pragma unroll
    for (int i = 0; i < 2; i++) {
        int f = wid * 2 + i;
        int mt = f >> 2, ks = f & 3;
        int r1 = mt * 16 + g;
        int c0 = ks * 16 + 2 * q;
        float2 p0 = *(const float2*)(Xp + r1 * 68 + c0);
        float2 p1 = *(const float2*)(Xp + (r1 + 8) * 68 + c0);
        float2 p2 = *(const float2*)(Xp + r1 * 68 + c0 + 8);
        float2 p3 = *(const float2*)(Xp + (r1 + 8) * 68 + c0 + 8);
        __half h0a, l0a, h0b, l0b, h1a, l1a, h1b, l1b;
        __half h2a, l2a, h2b, l2b, h3a, l3a, h3b, l3b;
        split_h(p0.x, h0a, l0a); split_h(p0.y, h0b, l0b);
        split_h(p1.x, h1a, l1a); split_h(p1.y, h1b, l1b);
        split_h(p2.x, h2a, l2a); split_h(p2.y, h2b, l2b);
        split_h(p3.x, h3a, l3a); split_h(p3.y, h3b, l3b);
        uint4 H = make_uint4(pack2(h0a, h0b), pack2(h1a, h1b), pack2(h2a, h2b), pack2(h3a, h3b));
        uint4 L = make_uint4(pack2(l0a, l0b), pack2(l1a, l1b), pack2(l2a, l2b), pack2(l3a, l3b));
        *(uint4*)(sm + AH_OFF + (f * 32 + lid) * 16) = H;
        *(uint4*)(sm + AL_OFF + (f * 32 + lid) * 16) = L;
    }
    __syncthreads();

    // ---- mainloop: warp (mw, nw): rows mw*32..+31, cols nw*64..+63 ----
    const int mw = wid & 1;
    const int nw = wid >> 1;            // 0..3
    float acc[2][8][4];
    #pragma unroll
    for (int mt = 0; mt < 2; mt++)
        #pragma unroll
        for (int nt = 0; nt < 8; nt++)
            #pragma unroll
            for (int e = 0; e < 4; e++) acc[mt][nt][e] = 0.0f;

    const uint2* bH = g_bfH + ((size_t)n * 128) * 32 + lid;
    const uint2* bL = g_bfL + ((size_t)n * 128) * 32 + lid;

    #pragma unroll
    for (int ks = 0; ks < 4; ks++) {
        uint4 ah0 = *(const uint4*)(sm + AH_OFF + (((2 * mw) * 4 + ks) * 32 + lid) * 16);
        uint4 al0 = *(const uint4*)(sm + AL_OFF + (((2 * mw) * 4 + ks) * 32 + lid) * 16);
        uint4 ah1 = *(const uint4*)(sm + AH_OFF + (((2 * mw + 1) * 4 + ks) * 32 + lid) * 16);
        uint4 al1 = *(const uint4*)(sm + AL_OFF + (((2 * mw + 1) * 4 + ks) * 32 + lid) * 16);
        #pragma unroll
        for (int nt = 0; nt < 8; nt++) {
            int f = (8 * nw + nt) * 4 + ks;
            uint2 bh = __ldg(bH + f * 32);
            uint2 bl = __ldg(bL + f * 32);
            mma_f16(acc[0][nt], (const uint32_t*)&ah0, bl.x, bl.y);   // h*l
            mma_f16(acc[0][nt], (const uint32_t*)&al0, bh.x, bh.y);   // l*h
            mma_f16(acc[0][nt], (const uint32_t*)&ah0, bh.x, bh.y);   // h*h
            mma_f16(acc[1][nt], (const uint32_t*)&ah1, bl.x, bl.y);
            mma_f16(acc[1][nt], (const uint32_t*)&al1, bh.x, bh.y);
            mma_f16(acc[1][nt], (const uint32_t*)&ah1, bh.x, bh.y);
        }
    }

    // ---- epilogue: rdist + argmin (lowest-index ties) ----
    float ccv[16];
    #pragma unroll
    for (int nt = 0; nt < 8; nt++) {
        float2 cp = *(const float2*)(cc + 64 * nw + 8 * nt + 2 * q);
        ccv[2 * nt] = cp.x; ccv[2 * nt + 1] = cp.y;
    }
    #pragma unroll
    for (int mt = 0; mt < 2; mt++) {
        #pragma unroll
        for (int rr = 0; rr < 2; rr++) {
            int lrow = mw * 32 + mt * 16 + rr * 8 + g;
            float A = As[lrow];
            float v = 0.0f; int bi = -1;
            #pragma unroll
            for (int nt = 0; nt < 8; nt++) {
                #pragma unroll
                for (int e = 0; e < 2; e++) {
                    float dot = acc[mt][nt][rr * 2 + e] * CUNSCALE;   // exact /64
                    float s = rdist(A, dot, ccv[2 * nt + e]);
                    int ci = 64 * nw + 8 * nt + 2 * q + e;
                    if (bi < 0 || s < v) { v = s; bi = ci; }
                }
            }
            #pragma unroll
            for (int off = 1; off <= 2; off <<= 1) {
                float ov = __shfl_xor_sync(0xffffffffu, v, off);
                int   oi = __shfl_xor_sync(0xffffffffu, bi, off);
                if (ov < v || (ov == v && oi < bi)) { v = ov; bi = oi; }
            }
            if (q == 0) {
                cand_v[lrow * 4 + nw] = v;
                cand_i[lrow * 4 + nw] = bi;
            }
        }
    }
    __syncthreads();

    // ---- combine 4 n-block candidates per row, write codes/counts ----
    if (tid < 64) {
        float v = cand_v[tid * 4];
        int bi = cand_i[tid * 4];
        #pragma unroll
        for (int p = 1; p < 4; p++) {
            float s = cand_v[tid * 4 + p];
            int si = cand_i[tid * 4 + p];
            if (s < v) { v = s; bi = si; }
        }
        codes_sm[tid] = bi;
        codes_out[(size_t)(row0 + tid) * NBOOKS + n] = (float)bi;
        atomicAdd(&g_counts[n * KCODES + bi], 1.0f);
    }
    __syncthreads();

    // ---- dw scatter: warp per 8 rows ----
    {
        const int rb = wid * 8;
        #pragma unroll
        for (int i = 0; i < 8; i++) {
            int r = rb + i;
            int bi = codes_sm[r];
            float xa = Xp[r * 68 + lid];
            float xb = Xp[r * 68 + lid + 32];
            float* dst = &g_dw[((size_t)(n * KCODES + bi)) * 64];
            atomicAdd(dst + lid, xa);
            atomicAdd(dst + lid + 32, xb);
        }
    }
}

// EMA update + write count/weight/codebook outputs.
__global__ void ema_kernel(const float* __restrict__ ec, const float* __restrict__ ew,
                           float* out)
{
    int i = blockIdx.x * blockDim.x + threadIdx.x;
    if (i >= NBOOKS * KCODES * 16) return;
    int d4 = i & 15;
    int nk = i >> 4;
    float nc = DECAY_F * ec[nk] + OMDECAY_F * g_counts[nk];
    float4 w  = *(const float4*)(ew + (size_t)nk * 64 + d4 * 4);
    float4 dv = *(const float4*)(g_dw + (size_t)nk * 64 + d4 * 4);
    float4 nw;
    nw.x = DECAY_F * w.x + OMDECAY_F * dv.x;
    nw.y = DECAY_F * w.y + OMDECAY_F * dv.y;
    nw.z = DECAY_F * w.z + OMDECAY_F * dv.z;
    nw.w = DECAY_F * w.w + OMDECAY_F * dv.w;
    float den = nc + EPS_F;
    float4 cbv;
    cbv.x = nw.x / den; cbv.y = nw.y / den; cbv.z = nw.z / den; cbv.w = nw.w / den;
    *(float4*)(out + OFF_W  + (size_t)nk * 64 + d4 * 4) = nw;
    *(float4*)(out + OFF_CB + (size_t)nk * 64 + d4 * 4) = cbv;
    if (d4 == 0) out[OFF_CNT + nk] = nc;
}

// recon gather, 2 independent chains per thread for ILP
#define RECON_HALF (BATCH * NBOOKS * 16 / 2)
__global__ void recon_kernel(float* out)
{
    int idx = blockIdx.x * blockDim.x + threadIdx.x;
    #pragma unroll
    for (int h = 0; h < 2; h++) {
        int i = idx + h * RECON_HALF;
        int d4 = i & 15;
        int bn = i >> 4;
        int n  = bn & 15;
        int b  = bn >> 4;
        int k  = (int)out[OFF_CODES + bn];
        float4 v = *(const float4*)(out + OFF_CB + ((size_t)(n * KCODES + k)) * 64 + d4 * 4);
        *(float4*)(out + OFF_RECON + (size_t)b * 1024 + n * 64 + d4 * 4) = v;
    }
}

extern "C" void kernel_launch(void* const* d_in, const int* in_sizes, int n_in,
                              void* d_out, int out_size)
{
    const float* x   = (const float*)d_in[0];
    const float* cbk = (const float*)d_in[1];
    const float* ec  = (const float*)d_in[2];
    const float* ew  = (const float*)d_in[3];
    float* out = (float*)d_out;

    prep_kernel<<<NBOOKS, 256>>>(cbk);
    dim3 grid(BATCH / 64, NBOOKS);
    assign_kernel<<<grid, 256, SM_BYTES>>>(x, out + OFF_CODES);
    ema_kernel<<<(NBOOKS * KCODES * 16) / 256, 256>>>(ec, ew, out);
    recon_kernel<<<RECON_HALF / 256, 256>>>(out);
}